// round 2
// baseline (speedup 1.0000x reference)
#include <cuda_runtime.h>
#include <math.h>
#include <stdint.h>

// ---------------------------------------------------------------------------
// LSTM: B=128, T=256, In=512, H=1024, Out=512
// Phase 0: pack gate weights interleaved  n = j*4 + g  (g: 0=f,1=i,2=c,3=o)
// Phase 1: GX[m, n] = x[m,:] . Wxp[n,:] + bp[n]        (m = b*256 + t)
// Phase 2: per t: GH = h_t . Whp^T ; fused gate epilogue updates c, h, HS
// Phase 3: out[m, o] = HS[m,:] . W_out[o,:] + b_out[o]
// ---------------------------------------------------------------------------

#define B_   128
#define T_   256
#define IN_  512
#define H_   1024
#define G4_  4096           // 4*H
#define OUT_ 512
#define M_   (B_ * T_)      // 32768

// Scratch (device globals: allocation-free rule)
__device__ float g_Wxp[(size_t)G4_ * IN_];     //  8 MB  packed x-part weights [4096,512]
__device__ float g_Whp[(size_t)G4_ * H_];      // 16 MB  packed h-part weights [4096,1024]
__device__ float g_bp [G4_];                   // packed bias
__device__ float g_GX [(size_t)M_ * G4_];      // 512 MB input-projection gates
__device__ float g_HS [(size_t)M_ * H_];       // 128 MB hidden states (all t)
__device__ float g_h  [2][B_ * H_];            // ping-pong h
__device__ float g_c  [B_ * H_];               // cell state

__device__ __forceinline__ float sigmf(float x) { return 1.0f / (1.0f + expf(-x)); }

// ---------------------------------------------------------------------------
// Phase 0: pack weights. blockIdx.x = n (0..4095). 128 threads.
// ---------------------------------------------------------------------------
__global__ void pack_weights(const float* __restrict__ Wf, const float* __restrict__ Wi,
                             const float* __restrict__ Wc, const float* __restrict__ Wo,
                             const float* __restrict__ bf, const float* __restrict__ bi,
                             const float* __restrict__ bc, const float* __restrict__ bo)
{
    int n = blockIdx.x;
    int j = n >> 2;
    int g = n & 3;
    const float* W = (g == 0) ? Wf : (g == 1) ? Wi : (g == 2) ? Wc : Wo;
    const float* row = W + (size_t)j * (IN_ + H_);
    for (int k = threadIdx.x; k < IN_; k += blockDim.x)
        g_Wxp[(size_t)n * IN_ + k] = row[k];
    for (int k = threadIdx.x; k < H_; k += blockDim.x)
        g_Whp[(size_t)n * H_ + k] = row[IN_ + k];
    if (threadIdx.x == 0) {
        const float* bb = (g == 0) ? bf : (g == 1) ? bi : (g == 2) ? bc : bo;
        g_bp[n] = bb[j];
    }
}

// ---------------------------------------------------------------------------
// Generic NT SGEMM: C[M,N] = A[M,K] * B[N,K]^T + bias[N]
// 128x128 tile, BK=8, 256 threads, 8x8 per thread. All dims multiple of 128/8.
// ---------------------------------------------------------------------------
__global__ void __launch_bounds__(256)
sgemm_nt(const float* __restrict__ A, const float* __restrict__ Bm,
         const float* __restrict__ bias, float* __restrict__ C,
         int Mdim, int Ndim, int Kdim)
{
    __shared__ float As[8][128];
    __shared__ float Bs[8][128];

    const int tid = threadIdx.x;
    const int m0 = blockIdx.y * 128;
    const int n0 = blockIdx.x * 128;

    const int ldRow = tid >> 1;          // 0..127
    const int ldK   = (tid & 1) * 4;     // 0 or 4

    const float* Aptr = A + (size_t)(m0 + ldRow) * Kdim + ldK;
    const float* Bptr = Bm + (size_t)(n0 + ldRow) * Kdim + ldK;

    const int ty = tid >> 4;             // 0..15  (row group)
    const int tx = tid & 15;             // 0..15  (col group)

    float acc[8][8];
#pragma unroll
    for (int i = 0; i < 8; i++)
#pragma unroll
        for (int j = 0; j < 8; j++) acc[i][j] = 0.0f;

    for (int k0 = 0; k0 < Kdim; k0 += 8) {
        float4 av = *(const float4*)(Aptr + k0);
        float4 bv = *(const float4*)(Bptr + k0);
        As[ldK + 0][ldRow] = av.x;
        As[ldK + 1][ldRow] = av.y;
        As[ldK + 2][ldRow] = av.z;
        As[ldK + 3][ldRow] = av.w;
        Bs[ldK + 0][ldRow] = bv.x;
        Bs[ldK + 1][ldRow] = bv.y;
        Bs[ldK + 2][ldRow] = bv.z;
        Bs[ldK + 3][ldRow] = bv.w;
        __syncthreads();

#pragma unroll
        for (int kk = 0; kk < 8; kk++) {
            float ar[8], br[8];
            *(float4*)(ar)     = *(const float4*)&As[kk][ty * 8];
            *(float4*)(ar + 4) = *(const float4*)&As[kk][ty * 8 + 4];
            *(float4*)(br)     = *(const float4*)&Bs[kk][tx * 8];
            *(float4*)(br + 4) = *(const float4*)&Bs[kk][tx * 8 + 4];
#pragma unroll
            for (int i = 0; i < 8; i++)
#pragma unroll
                for (int j = 0; j < 8; j++)
                    acc[i][j] = fmaf(ar[i], br[j], acc[i][j]);
        }
        __syncthreads();
    }

    // epilogue: add bias, vectorized stores
#pragma unroll
    for (int i = 0; i < 8; i++) {
        float* crow = C + (size_t)(m0 + ty * 8 + i) * Ndim + n0 + tx * 8;
        const float* brow = bias + n0 + tx * 8;
        float4 v0, v1;
        v0.x = acc[i][0] + brow[0];
        v0.y = acc[i][1] + brow[1];
        v0.z = acc[i][2] + brow[2];
        v0.w = acc[i][3] + brow[3];
        v1.x = acc[i][4] + brow[4];
        v1.y = acc[i][5] + brow[5];
        v1.z = acc[i][6] + brow[6];
        v1.w = acc[i][7] + brow[7];
        *(float4*)(crow)     = v0;
        *(float4*)(crow + 4) = v1;
    }
}

// ---------------------------------------------------------------------------
// Phase 2: one timestep. GH = h_in[128,1024] . Whp[4096,1024]^T, tile 128x32.
// grid.x = 128 tiles over N=4096. 128 threads: 16 row-groups(TM=8) x 8 col-
// groups(TN=4). Because n = j*4+g, each thread's 4 contiguous cols are the
// complete gate quad for one j -> fused activation + c/h update in epilogue.
// ---------------------------------------------------------------------------
__global__ void __launch_bounds__(128)
lstm_step(int t)
{
    __shared__ float As[16][128];   // h tile, [k][b]
    __shared__ float Bs[16][32];    // Whp tile, [k][n]

    const float* __restrict__ h_in = g_h[t & 1];
    float* __restrict__ h_out      = g_h[(t + 1) & 1];

    const int tid = threadIdx.x;
    const int n0  = blockIdx.x * 32;

    const int rg = tid >> 3;        // 0..15 row group (8 rows each)
    const int cg = tid & 7;         // 0..7 col group (4 cols each)

    const int bn = tid >> 2;        // 0..31 : n-row this thread loads for B
    const int bk = (tid & 3) * 4;   // k offset within chunk

    float acc[8][4];
#pragma unroll
    for (int i = 0; i < 8; i++)
#pragma unroll
        for (int j = 0; j < 4; j++) acc[i][j] = 0.0f;

    const float* Bbase = g_Whp + (size_t)(n0 + bn) * H_ + bk;

    for (int k0 = 0; k0 < H_; k0 += 16) {
        // load h tile: thread = row b (tid), 16 k values as 4 float4
        const float* hrow = h_in + (size_t)tid * H_ + k0;
#pragma unroll
        for (int q = 0; q < 4; q++) {
            float4 v = *(const float4*)(hrow + q * 4);
            As[q * 4 + 0][tid] = v.x;
            As[q * 4 + 1][tid] = v.y;
            As[q * 4 + 2][tid] = v.z;
            As[q * 4 + 3][tid] = v.w;
        }
        // load W tile
        {
            float4 v = *(const float4*)(Bbase + k0);
            Bs[bk + 0][bn] = v.x;
            Bs[bk + 1][bn] = v.y;
            Bs[bk + 2][bn] = v.z;
            Bs[bk + 3][bn] = v.w;
        }
        __syncthreads();

#pragma unroll
        for (int kk = 0; kk < 16; kk++) {
            float ar[8], br[4];
            *(float4*)(ar)     = *(const float4*)&As[kk][rg * 8];
            *(float4*)(ar + 4) = *(const float4*)&As[kk][rg * 8 + 4];
            *(float4*)(br)     = *(const float4*)&Bs[kk][cg * 4];
#pragma unroll
            for (int i = 0; i < 8; i++)
#pragma unroll
                for (int j = 0; j < 4; j++)
                    acc[i][j] = fmaf(ar[i], br[j], acc[i][j]);
        }
        __syncthreads();
    }

    // fused gate epilogue
    const int n4 = n0 + cg * 4;     // first col of the gate quad
    const int j  = n4 >> 2;         // hidden unit index
#pragma unroll
    for (int i = 0; i < 8; i++) {
        const int b = rg * 8 + i;
        const size_t m = (size_t)b * T_ + t;
        const float* gx = g_GX + m * G4_ + n4;
        float gf = acc[i][0] + gx[0];
        float gi = acc[i][1] + gx[1];
        float gc = acc[i][2] + gx[2];
        float go = acc[i][3] + gx[3];
        float f  = sigmf(gf);
        float ig = sigmf(gi);
        float ct = tanhf(gc);
        float o  = sigmf(go);
        const int cidx = b * H_ + j;
        float cn = f * g_c[cidx] + ig * ct;
        g_c[cidx] = cn;
        float hn = o * tanhf(cn);
        h_out[cidx] = hn;
        g_HS[m * H_ + j] = hn;
    }
}

// ---------------------------------------------------------------------------
// Host launcher
// ---------------------------------------------------------------------------
extern "C" void kernel_launch(void* const* d_in, const int* in_sizes, int n_in,
                              void* d_out, int out_size)
{
    (void)in_sizes; (void)n_in; (void)out_size;

    const float* x     = (const float*)d_in[0];
    const float* W_f   = (const float*)d_in[1];
    const float* b_f   = (const float*)d_in[2];
    const float* W_i   = (const float*)d_in[3];
    const float* b_i   = (const float*)d_in[4];
    const float* W_c   = (const float*)d_in[5];
    const float* b_c   = (const float*)d_in[6];
    const float* W_o   = (const float*)d_in[7];
    const float* b_o   = (const float*)d_in[8];
    const float* W_out = (const float*)d_in[9];
    const float* b_out = (const float*)d_in[10];
    float* out = (float*)d_out;

    // symbol addresses (query only; not an allocation)
    void *p_wxp, *p_bp, *p_gx, *p_hs, *p_h, *p_c;
    cudaGetSymbolAddress(&p_wxp, g_Wxp);
    cudaGetSymbolAddress(&p_bp,  g_bp);
    cudaGetSymbolAddress(&p_gx,  g_GX);
    cudaGetSymbolAddress(&p_hs,  g_HS);
    cudaGetSymbolAddress(&p_h,   g_h);
    cudaGetSymbolAddress(&p_c,   g_c);

    // zero initial state (h ping buffer 0 and c); pong buffer is fully
    // written at t=0 before its first read, so only buffer 0 needs zeroing.
    // t=255 writes g_h[0], which this memset re-zeroes on every graph replay.
    cudaMemsetAsync(p_h, 0, (size_t)B_ * H_ * sizeof(float));
    cudaMemsetAsync(p_c, 0, (size_t)B_ * H_ * sizeof(float));

    // Phase 0: pack weights
    pack_weights<<<G4_, 128>>>(W_f, W_i, W_c, W_o, b_f, b_i, b_c, b_o);

    // Phase 1: GX = x @ Wxp^T + bp   (M=32768, N=4096, K=512)
    {
        dim3 grid(G4_ / 128, M_ / 128);
        sgemm_nt<<<grid, 256>>>(x, (const float*)p_wxp, (const float*)p_bp,
                                (float*)p_gx, M_, G4_, IN_);
    }

    // Phase 2: 256 recurrent steps, fully fused
    for (int t = 0; t < T_; t++) {
        lstm_step<<<G4_ / 32, 128>>>(t);
    }

    // Phase 3: out = HS @ W_out^T + b_out  (M=32768, N=512, K=1024)
    {
        dim3 grid(OUT_ / 128, M_ / 128);
        sgemm_nt<<<grid, 256>>>((const float*)p_hs, W_out, b_out,
                                out, M_, OUT_, H_);
    }
}

// round 3
// speedup vs baseline: 1.9118x; 1.9118x over previous
#include <cuda_runtime.h>
#include <math.h>
#include <stdint.h>

// ---------------------------------------------------------------------------
// LSTM: B=128, T=256, In=512, H=1024, Out=512
// Phase 0: pack gate weights PLANAR  n = g*1024 + j  (g: 0=f,1=i,2=c,3=o)
//          Whp stored as tf32 bit patterns.
// Phase 1: GX[m, n] = x[m,:] . Wxp[n,:] + bp[n]   (fp32 SGEMM, m = b*256 + t)
// Phase 2: per t: GH = h_t . Whp^T  via mma.sync tf32; fused gate epilogue
// Phase 3: out[m, o] = HS[m,:] . W_out[o,:] + b_out[o]  (fp32 SGEMM)
// ---------------------------------------------------------------------------

#define B_   128
#define T_   256
#define IN_  512
#define H_   1024
#define G4_  4096
#define OUT_ 512
#define M_   (B_ * T_)      // 32768

__device__ float    g_Wxp[(size_t)G4_ * IN_];   // packed x-part weights (fp32)
__device__ uint32_t g_Whp[(size_t)G4_ * H_];    // packed h-part weights (tf32 bits)
__device__ float    g_bp [G4_];                 // packed bias
__device__ float    g_GX [(size_t)M_ * G4_];    // input-projection gates
__device__ float    g_HS [(size_t)M_ * H_];     // hidden states (all t)
__device__ float    g_h  [2][B_ * H_];          // ping-pong h
__device__ float    g_c  [B_ * H_];             // cell state

__device__ __forceinline__ float sigmf(float x) { return 1.0f / (1.0f + expf(-x)); }

__device__ __forceinline__ uint32_t f2tf32(float x) {
    uint32_t r;
    asm("cvt.rna.tf32.f32 %0, %1;" : "=r"(r) : "f"(x));
    return r;
}

__device__ __forceinline__ void mma_tf32(float c[4], uint32_t a0, uint32_t a1,
                                         uint32_t a2, uint32_t a3,
                                         uint32_t b0, uint32_t b1) {
    asm volatile(
        "mma.sync.aligned.m16n8k8.row.col.f32.tf32.tf32.f32 "
        "{%0,%1,%2,%3}, {%4,%5,%6,%7}, {%8,%9}, {%0,%1,%2,%3};"
        : "+f"(c[0]), "+f"(c[1]), "+f"(c[2]), "+f"(c[3])
        : "r"(a0), "r"(a1), "r"(a2), "r"(a3), "r"(b0), "r"(b1));
}

// ---------------------------------------------------------------------------
// Phase 0: pack weights planar. blockIdx.x = n (0..4095). 128 threads.
// ---------------------------------------------------------------------------
__global__ void pack_weights(const float* __restrict__ Wf, const float* __restrict__ Wi,
                             const float* __restrict__ Wc, const float* __restrict__ Wo,
                             const float* __restrict__ bf, const float* __restrict__ bi,
                             const float* __restrict__ bc, const float* __restrict__ bo)
{
    int n = blockIdx.x;
    int g = n >> 10;
    int j = n & 1023;
    const float* W = (g == 0) ? Wf : (g == 1) ? Wi : (g == 2) ? Wc : Wo;
    const float* row = W + (size_t)j * (IN_ + H_);
    for (int k = threadIdx.x; k < IN_; k += blockDim.x)
        g_Wxp[(size_t)n * IN_ + k] = row[k];
    for (int k = threadIdx.x; k < H_; k += blockDim.x)
        g_Whp[(size_t)n * H_ + k] = f2tf32(row[IN_ + k]);
    if (threadIdx.x == 0) {
        const float* bb = (g == 0) ? bf : (g == 1) ? bi : (g == 2) ? bc : bo;
        g_bp[n] = bb[j];
    }
}

// ---------------------------------------------------------------------------
// Generic NT SGEMM: C[M,N] = A[M,K] * B[N,K]^T + bias[N]   (fp32)
// ---------------------------------------------------------------------------
__global__ void __launch_bounds__(256)
sgemm_nt(const float* __restrict__ A, const float* __restrict__ Bm,
         const float* __restrict__ bias, float* __restrict__ C,
         int Mdim, int Ndim, int Kdim)
{
    __shared__ float As[8][128];
    __shared__ float Bs[8][128];

    const int tid = threadIdx.x;
    const int m0 = blockIdx.y * 128;
    const int n0 = blockIdx.x * 128;

    const int ldRow = tid >> 1;
    const int ldK   = (tid & 1) * 4;

    const float* Aptr = A + (size_t)(m0 + ldRow) * Kdim + ldK;
    const float* Bptr = Bm + (size_t)(n0 + ldRow) * Kdim + ldK;

    const int ty = tid >> 4;
    const int tx = tid & 15;

    float acc[8][8];
#pragma unroll
    for (int i = 0; i < 8; i++)
#pragma unroll
        for (int j = 0; j < 8; j++) acc[i][j] = 0.0f;

    for (int k0 = 0; k0 < Kdim; k0 += 8) {
        float4 av = *(const float4*)(Aptr + k0);
        float4 bv = *(const float4*)(Bptr + k0);
        As[ldK + 0][ldRow] = av.x;
        As[ldK + 1][ldRow] = av.y;
        As[ldK + 2][ldRow] = av.z;
        As[ldK + 3][ldRow] = av.w;
        Bs[ldK + 0][ldRow] = bv.x;
        Bs[ldK + 1][ldRow] = bv.y;
        Bs[ldK + 2][ldRow] = bv.z;
        Bs[ldK + 3][ldRow] = bv.w;
        __syncthreads();

#pragma unroll
        for (int kk = 0; kk < 8; kk++) {
            float ar[8], br[8];
            *(float4*)(ar)     = *(const float4*)&As[kk][ty * 8];
            *(float4*)(ar + 4) = *(const float4*)&As[kk][ty * 8 + 4];
            *(float4*)(br)     = *(const float4*)&Bs[kk][tx * 8];
            *(float4*)(br + 4) = *(const float4*)&Bs[kk][tx * 8 + 4];
#pragma unroll
            for (int i = 0; i < 8; i++)
#pragma unroll
                for (int j = 0; j < 8; j++)
                    acc[i][j] = fmaf(ar[i], br[j], acc[i][j]);
        }
        __syncthreads();
    }

#pragma unroll
    for (int i = 0; i < 8; i++) {
        float* crow = C + (size_t)(m0 + ty * 8 + i) * Ndim + n0 + tx * 8;
        const float* brow = bias + n0 + tx * 8;
        float4 v0, v1;
        v0.x = acc[i][0] + brow[0];
        v0.y = acc[i][1] + brow[1];
        v0.z = acc[i][2] + brow[2];
        v0.w = acc[i][3] + brow[3];
        v1.x = acc[i][4] + brow[4];
        v1.y = acc[i][5] + brow[5];
        v1.z = acc[i][6] + brow[6];
        v1.w = acc[i][7] + brow[7];
        *(float4*)(crow)     = v0;
        *(float4*)(crow + 4) = v1;
    }
}

// ---------------------------------------------------------------------------
// Phase 2: one timestep via tensor cores.
// grid = (128, 2): blockIdx.x -> j-tile of 8 hidden units, blockIdx.y -> M half.
// block = 128 threads (4 warps). Warp w handles rows [mbase+16w, mbase+16w+16).
// Each warp: 4 accumulators m16n8 (one per gate f/i/c/o) sharing one A frag.
// Epilogue: complete gate math in registers (fragments align across gates).
// ---------------------------------------------------------------------------
#define KC 32

__global__ void __launch_bounds__(128)
lstm_step_mma(int t)
{
    __shared__ uint32_t sh_h[64][36];   // [m local][k local], tf32 bits, padded
    __shared__ uint32_t sh_w[32][36];   // [g*8+jj][k local], tf32 bits, padded

    const int tid  = threadIdx.x;
    const int lane = tid & 31;
    const int warp = tid >> 5;
    const int j0    = blockIdx.x * 8;
    const int mbase = blockIdx.y * 64;

    const float* __restrict__ h_in = g_h[t & 1];
    float* __restrict__ h_out      = g_h[(t + 1) & 1];

    float acc[4][4];
#pragma unroll
    for (int g = 0; g < 4; g++)
#pragma unroll
        for (int i = 0; i < 4; i++) acc[g][i] = 0.0f;

    // W loader: gj = tid>>2 (0..31) -> gate g = gj>>3, jj = gj&7.
    const int gj   = tid >> 2;
    const int wrow = (gj >> 3) * H_ + j0 + (gj & 7);
    const uint32_t* __restrict__ Wrow = g_Whp + (size_t)wrow * H_;
    const int wq = (tid & 3) * 4;       // k quad offset (0,4,8,12), +16 for second

    // h loader: m = tid>>1 (0..63), k base (tid&1)*16
    const int hm = tid >> 1;
    const int hq = (tid & 1) * 16;
    const float* __restrict__ hrow = h_in + (size_t)(mbase + hm) * H_ + hq;

    const int r  = lane >> 2;           // fragment row group
    const int kq = lane & 3;            // fragment k group

    for (int k0 = 0; k0 < H_; k0 += KC) {
        // stage W tile (already tf32)
        uint4 w0 = *(const uint4*)(Wrow + k0 + wq);
        uint4 w1 = *(const uint4*)(Wrow + k0 + wq + 16);
        *(uint4*)&sh_w[gj][wq]      = w0;
        *(uint4*)&sh_w[gj][wq + 16] = w1;
        // stage h tile with tf32 convert
#pragma unroll
        for (int i = 0; i < 4; i++) {
            float4 v = *(const float4*)(hrow + k0 + i * 4);
            uint4 u;
            u.x = f2tf32(v.x); u.y = f2tf32(v.y);
            u.z = f2tf32(v.z); u.w = f2tf32(v.w);
            *(uint4*)&sh_h[hm][hq + i * 4] = u;
        }
        __syncthreads();

#pragma unroll
        for (int ks = 0; ks < 4; ks++) {
            const int kb = ks * 8;
            uint32_t a0 = sh_h[warp * 16 + r    ][kb + kq];
            uint32_t a1 = sh_h[warp * 16 + r + 8][kb + kq];
            uint32_t a2 = sh_h[warp * 16 + r    ][kb + kq + 4];
            uint32_t a3 = sh_h[warp * 16 + r + 8][kb + kq + 4];
#pragma unroll
            for (int g = 0; g < 4; g++) {
                uint32_t b0 = sh_w[g * 8 + r][kb + kq];
                uint32_t b1 = sh_w[g * 8 + r][kb + kq + 4];
                mma_tf32(acc[g], a0, a1, a2, a3, b0, b1);
            }
        }
        __syncthreads();
    }

    // fused gate epilogue: lane holds rows {r, r+8}, cols {2*kq, 2*kq+1}
    const int jc = j0 + 2 * kq;
#pragma unroll
    for (int rh = 0; rh < 2; rh++) {
        const int b = mbase + warp * 16 + r + rh * 8;
        const size_t m = (size_t)b * T_ + t;
        const float* gx = g_GX + m * G4_;
        float2 gxf = *(const float2*)(gx + 0 * H_ + jc);
        float2 gxi = *(const float2*)(gx + 1 * H_ + jc);
        float2 gxc = *(const float2*)(gx + 2 * H_ + jc);
        float2 gxo = *(const float2*)(gx + 3 * H_ + jc);
        float2 cold = *(const float2*)(g_c + b * H_ + jc);

        const int a0i = rh * 2, a1i = rh * 2 + 1;
        float f0 = sigmf(acc[0][a0i] + gxf.x);
        float f1 = sigmf(acc[0][a1i] + gxf.y);
        float i0 = sigmf(acc[1][a0i] + gxi.x);
        float i1 = sigmf(acc[1][a1i] + gxi.y);
        float t0 = tanhf(acc[2][a0i] + gxc.x);
        float t1 = tanhf(acc[2][a1i] + gxc.y);
        float o0 = sigmf(acc[3][a0i] + gxo.x);
        float o1 = sigmf(acc[3][a1i] + gxo.y);

        float cn0 = f0 * cold.x + i0 * t0;
        float cn1 = f1 * cold.y + i1 * t1;
        float hn0 = o0 * tanhf(cn0);
        float hn1 = o1 * tanhf(cn1);

        *(float2*)(g_c   + b * H_ + jc) = make_float2(cn0, cn1);
        *(float2*)(h_out + b * H_ + jc) = make_float2(hn0, hn1);
        *(float2*)(g_HS  + m * H_ + jc) = make_float2(hn0, hn1);
    }
}

// ---------------------------------------------------------------------------
// Host launcher
// ---------------------------------------------------------------------------
extern "C" void kernel_launch(void* const* d_in, const int* in_sizes, int n_in,
                              void* d_out, int out_size)
{
    (void)in_sizes; (void)n_in; (void)out_size;

    const float* x     = (const float*)d_in[0];
    const float* W_f   = (const float*)d_in[1];
    const float* b_f   = (const float*)d_in[2];
    const float* W_i   = (const float*)d_in[3];
    const float* b_i   = (const float*)d_in[4];
    const float* W_c   = (const float*)d_in[5];
    const float* b_c   = (const float*)d_in[6];
    const float* W_o   = (const float*)d_in[7];
    const float* b_o   = (const float*)d_in[8];
    const float* W_out = (const float*)d_in[9];
    const float* b_out = (const float*)d_in[10];
    float* out = (float*)d_out;

    void *p_wxp, *p_bp, *p_gx, *p_hs, *p_h, *p_c;
    cudaGetSymbolAddress(&p_wxp, g_Wxp);
    cudaGetSymbolAddress(&p_bp,  g_bp);
    cudaGetSymbolAddress(&p_gx,  g_GX);
    cudaGetSymbolAddress(&p_hs,  g_HS);
    cudaGetSymbolAddress(&p_h,   g_h);
    cudaGetSymbolAddress(&p_c,   g_c);

    // zero initial state; t=255 writes g_h[0], re-zeroed on every replay.
    cudaMemsetAsync(p_h, 0, (size_t)B_ * H_ * sizeof(float));
    cudaMemsetAsync(p_c, 0, (size_t)B_ * H_ * sizeof(float));

    // Phase 0: pack weights (planar; Whp -> tf32)
    pack_weights<<<G4_, 128>>>(W_f, W_i, W_c, W_o, b_f, b_i, b_c, b_o);

    // Phase 1: GX = x @ Wxp^T + bp   (M=32768, N=4096, K=512)
    {
        dim3 grid(G4_ / 128, M_ / 128);
        sgemm_nt<<<grid, 256>>>(x, (const float*)p_wxp, (const float*)p_bp,
                                (float*)p_gx, M_, G4_, IN_);
    }

    // Phase 2: 256 recurrent steps (tensor-core, fused epilogue)
    for (int t = 0; t < T_; t++) {
        dim3 grid(H_ / 8, 2);
        lstm_step_mma<<<grid, 128>>>(t);
    }

    // Phase 3: out = HS @ W_out^T + b_out  (M=32768, N=512, K=1024)
    {
        dim3 grid(OUT_ / 128, M_ / 128);
        sgemm_nt<<<grid, 256>>>((const float*)p_hs, W_out, b_out,
                                out, M_, OUT_, H_);
    }
}